// round 12
// baseline (speedup 1.0000x reference)
#include <cuda_runtime.h>
#include <cstdint>

// HashEncoding: 5-level instant-NGP trilinear hash grid lookup.
//   N = in_sizes[0]/3 points, tables [5, 2^20, 4] fp32, out [N, 20] fp32.
// R12: UNIFIED LOAD ISSUE. Previously even/odd-bx branches serialized: mixed
// warps stalled on the even path's FMAs (long_scoreboard) before the odd
// path's loads could issue -> two memory-latency exposures per item. Now ALL
// lanes issue 4 pair-loads (i&~1; odd lanes get corner x0 + a weight-0
// garbage neighbor) plus 4 predicated v4 loads (odd lanes' x1 corners,
// zero-init for even lanes). Same wavefront count as champion, single
// latency exposure, one FMA chain. 48 warps/SM at ~40 regs.

#define HASH_BITS   20
#define HASH_MASK   ((1u << HASH_BITS) - 1u)
#define NUM_LEVELS  5
#define PI2 19349663u
#define PI3 83492791u

__device__ __forceinline__ void ld_pair(const float4* p, unsigned long long pol,
                                        float4& lo, float4& hi) {
    asm("ld.global.nc.L2::cache_hint.v8.b32 {%0,%1,%2,%3,%4,%5,%6,%7}, [%8], %9;"
        : "=f"(lo.x), "=f"(lo.y), "=f"(lo.z), "=f"(lo.w),
          "=f"(hi.x), "=f"(hi.y), "=f"(hi.z), "=f"(hi.w)
        : "l"(p), "l"(pol));
}

__device__ __forceinline__ float4 ld_tab(const float4* p, unsigned long long pol) {
    float4 v;
    asm("ld.global.nc.L2::cache_hint.v4.f32 {%0,%1,%2,%3}, [%4], %5;"
        : "=f"(v.x), "=f"(v.y), "=f"(v.z), "=f"(v.w) : "l"(p), "l"(pol));
    return v;
}

__device__ __forceinline__ void st_stream(float4* p, float4 v) {
    asm volatile("st.global.cs.v4.f32 [%0], {%1,%2,%3,%4};"
                 :: "l"(p), "f"(v.x), "f"(v.y), "f"(v.z), "f"(v.w) : "memory");
}

__global__ void __launch_bounds__(256, 6)
hashenc_kernel(const float* __restrict__ x,
               const float4* __restrict__ tables,
               float4* __restrict__ out,
               int n_points)
{
    int tid = blockIdx.x * blockDim.x + threadIdx.x;
    int total = n_points * NUM_LEVELS;
    if (tid >= total) return;

    int n = tid / NUM_LEVELS;
    int l = tid - n * NUM_LEVELS;

    unsigned long long pol;
    asm("createpolicy.fractional.L2::evict_last.b64 %0, 1.0;" : "=l"(pol));

    float cx = __ldg(x + n * 3 + 0);
    float cy = __ldg(x + n * 3 + 1);
    float cz = __ldg(x + n * 3 + 2);

    // x01 = (x + 2) / 4 ; loc = x01 * gs - 0.5 ; gs = 128 << l
    float gs = (float)(128 << l);
    float lx = (cx + 2.0f) * 0.25f * gs - 0.5f;
    float ly = (cy + 2.0f) * 0.25f * gs - 0.5f;
    float lz = (cz + 2.0f) * 0.25f * gs - 0.5f;

    float fx = floorf(lx), fy = floorf(ly), fz = floorf(lz);
    float wx1 = lx - fx, wy1 = ly - fy, wz1 = lz - fz;
    float wx0 = 1.0f - wx1, wy0 = 1.0f - wy1, wz0 = 1.0f - wz1;

    unsigned bx = (unsigned)(int)fx;
    unsigned by = (unsigned)(int)fy;
    unsigned bz = (unsigned)(int)fz;

    unsigned hy0 = by * PI2;
    unsigned hz0 = bz * PI3;
    unsigned dy  = hy0 ^ ((by + 1u) * PI2);
    unsigned dz  = hz0 ^ ((bz + 1u) * PI3);

    const float4* __restrict__ tab = tables + ((size_t)l << HASH_BITS);

    unsigned h000 = bx ^ hy0 ^ hz0;
    unsigned i000 = h000 & HASH_MASK;
    unsigned i001 = (h000 ^ dz) & HASH_MASK;
    unsigned i010 = (h000 ^ dy) & HASH_MASK;
    unsigned i011 = (h000 ^ dy ^ dz) & HASH_MASK;

    bool odd = (bx & 1u) != 0u;

    // x1-corner indices (needed as separate loads only for odd lanes)
    unsigned h100 = h000 ^ bx ^ (bx + 1u);
    unsigned i100 = h100 & HASH_MASK;
    unsigned i101 = (h100 ^ dz) & HASH_MASK;
    unsigned i110 = (h100 ^ dy) & HASH_MASK;
    unsigned i111 = (h100 ^ dy ^ dz) & HASH_MASK;

    // ---- unified load issue: 4 pair loads for ALL lanes ----
    float4 a0, b0, a1, b1, a2, b2, a3, b3;
    ld_pair(tab + (i000 & ~1u), pol, a0, b0);
    ld_pair(tab + (i001 & ~1u), pol, a1, b1);
    ld_pair(tab + (i010 & ~1u), pol, a2, b2);
    ld_pair(tab + (i011 & ~1u), pol, a3, b3);

    // ---- 4 extra x1-corner loads, odd lanes only (short predicated arm) ----
    float4 e0 = make_float4(0.f, 0.f, 0.f, 0.f);
    float4 e1 = e0, e2 = e0, e3 = e0;
    if (odd) {
        e0 = ld_tab(tab + i100, pol);
        e1 = ld_tab(tab + i101, pol);
        e2 = ld_tab(tab + i110, pol);
        e3 = ld_tab(tab + i111, pol);
    }

    // weights
    float w000 = (wx0 * wy0) * wz0;
    float w001 = (wx0 * wy0) * wz1;
    float w010 = (wx0 * wy1) * wz0;
    float w011 = (wx0 * wy1) * wz1;
    float w100 = (wx1 * wy0) * wz0;
    float w101 = (wx1 * wy0) * wz1;
    float w110 = (wx1 * wy1) * wz0;
    float w111 = (wx1 * wy1) * wz1;

    // pair-half weights: the half that is the x1 corner gets w1yz for even
    // lanes, 0 for odd lanes (garbage neighbor); ext loads get w1yz for odd.
    float p0 = odd ? 0.f : w100,  q0 = odd ? w100 : 0.f;
    float p1 = odd ? 0.f : w101,  q1 = odd ? w101 : 0.f;
    float p2 = odd ? 0.f : w110,  q2 = odd ? w110 : 0.f;
    float p3 = odd ? 0.f : w111,  q3 = odd ? w111 : 0.f;

    // lo half = even table index; if i0yz is odd, hi holds the x0 corner.
    float wl0 = (i000 & 1u) ? p0 : w000, wh0 = (i000 & 1u) ? w000 : p0;
    float wl1 = (i001 & 1u) ? p1 : w001, wh1 = (i001 & 1u) ? w001 : p1;
    float wl2 = (i010 & 1u) ? p2 : w010, wh2 = (i010 & 1u) ? w010 : p2;
    float wl3 = (i011 & 1u) ? p3 : w011, wh3 = (i011 & 1u) ? w011 : p3;

    float ax, ay, az, aw;
    ax = a0.x * wl0; ay = a0.y * wl0; az = a0.z * wl0; aw = a0.w * wl0;
    ax = fmaf(b0.x, wh0, ax); ay = fmaf(b0.y, wh0, ay); az = fmaf(b0.z, wh0, az); aw = fmaf(b0.w, wh0, aw);
    ax = fmaf(a1.x, wl1, ax); ay = fmaf(a1.y, wl1, ay); az = fmaf(a1.z, wl1, az); aw = fmaf(a1.w, wl1, aw);
    ax = fmaf(b1.x, wh1, ax); ay = fmaf(b1.y, wh1, ay); az = fmaf(b1.z, wh1, az); aw = fmaf(b1.w, wh1, aw);
    ax = fmaf(a2.x, wl2, ax); ay = fmaf(a2.y, wl2, ay); az = fmaf(a2.z, wl2, az); aw = fmaf(a2.w, wl2, aw);
    ax = fmaf(b2.x, wh2, ax); ay = fmaf(b2.y, wh2, ay); az = fmaf(b2.z, wh2, az); aw = fmaf(b2.w, wh2, aw);
    ax = fmaf(a3.x, wl3, ax); ay = fmaf(a3.y, wl3, ay); az = fmaf(a3.z, wl3, az); aw = fmaf(a3.w, wl3, aw);
    ax = fmaf(b3.x, wh3, ax); ay = fmaf(b3.y, wh3, ay); az = fmaf(b3.z, wh3, az); aw = fmaf(b3.w, wh3, aw);
    // ext x1 corners (odd lanes; zero weight and zero regs for even lanes)
    ax = fmaf(e0.x, q0, ax); ay = fmaf(e0.y, q0, ay); az = fmaf(e0.z, q0, az); aw = fmaf(e0.w, q0, aw);
    ax = fmaf(e1.x, q1, ax); ay = fmaf(e1.y, q1, ay); az = fmaf(e1.z, q1, az); aw = fmaf(e1.w, q1, aw);
    ax = fmaf(e2.x, q2, ax); ay = fmaf(e2.y, q2, ay); az = fmaf(e2.z, q2, az); aw = fmaf(e2.w, q2, aw);
    ax = fmaf(e3.x, q3, ax); ay = fmaf(e3.y, q3, ay); az = fmaf(e3.z, q3, az); aw = fmaf(e3.w, q3, aw);

    float4 r;
    r.x = ax * 10.0f;
    r.y = ay * 10.0f;
    r.z = az * 10.0f;
    r.w = aw * 10.0f;
    st_stream(out + (size_t)n * NUM_LEVELS + l, r);   // == out + tid, coalesced
}

extern "C" void kernel_launch(void* const* d_in, const int* in_sizes, int n_in,
                              void* d_out, int out_size)
{
    const float*  x      = (const float*)d_in[0];
    const float4* tables = (const float4*)d_in[1];
    float4*       out    = (float4*)d_out;

    int n_points = in_sizes[0] / 3;
    int total = n_points * NUM_LEVELS;
    int block = 256;
    int grid = (total + block - 1) / block;
    hashenc_kernel<<<grid, block>>>(x, tables, out, n_points);
}

// round 13
// speedup vs baseline: 1.2118x; 1.2118x over previous
#include <cuda_runtime.h>
#include <cstdint>

// HashEncoding: 5-level instant-NGP trilinear hash grid lookup.
//   N = in_sizes[0]/3 points, tables [5, 2^20, 4] fp32, out [N, 20] fp32.
// R13 = R5 champion (one thread per (point,level); x-corner pairing: even bx
// -> 4x 32B paired loads via i^1 adjacency; coalesced streaming stores;
// 32 regs / 8 blocks/SM; evict_last on all table loads) + L1::no_allocate on
// table gathers: random 80MB gathers never hit L1, so skip the useless L1
// fills (frees l1tex data-array bandwidth, keeps x-coords resident in L1).

#define HASH_BITS   20
#define HASH_MASK   ((1u << HASH_BITS) - 1u)
#define NUM_LEVELS  5
#define PI2 19349663u
#define PI3 83492791u

__device__ __forceinline__ void ld_pair(const float4* p, float4& lo, float4& hi) {
    asm("ld.global.nc.L1::no_allocate.L2::evict_last.v8.b32 "
        "{%0,%1,%2,%3,%4,%5,%6,%7}, [%8];"
        : "=f"(lo.x), "=f"(lo.y), "=f"(lo.z), "=f"(lo.w),
          "=f"(hi.x), "=f"(hi.y), "=f"(hi.z), "=f"(hi.w)
        : "l"(p));
}

__device__ __forceinline__ float4 ld_tab(const float4* p, unsigned long long pol) {
    float4 v;
    asm("ld.global.nc.L1::no_allocate.L2::cache_hint.v4.f32 "
        "{%0,%1,%2,%3}, [%4], %5;"
        : "=f"(v.x), "=f"(v.y), "=f"(v.z), "=f"(v.w) : "l"(p), "l"(pol));
    return v;
}

__device__ __forceinline__ void st_stream(float4* p, float4 v) {
    asm volatile("st.global.cs.v4.f32 [%0], {%1,%2,%3,%4};"
                 :: "l"(p), "f"(v.x), "f"(v.y), "f"(v.z), "f"(v.w) : "memory");
}

__global__ void __launch_bounds__(256, 8)
hashenc_kernel(const float* __restrict__ x,
               const float4* __restrict__ tables,
               float4* __restrict__ out,
               int n_points)
{
    int tid = blockIdx.x * blockDim.x + threadIdx.x;
    int total = n_points * NUM_LEVELS;
    if (tid >= total) return;

    int n = tid / NUM_LEVELS;
    int l = tid - n * NUM_LEVELS;

    unsigned long long pol;
    asm("createpolicy.fractional.L2::evict_last.b64 %0, 1.0;" : "=l"(pol));

    float cx = __ldg(x + n * 3 + 0);
    float cy = __ldg(x + n * 3 + 1);
    float cz = __ldg(x + n * 3 + 2);

    // x01 = (x + 2) / 4 ; loc = x01 * gs - 0.5 ; gs = 128 << l
    float gs = (float)(128 << l);
    float lx = (cx + 2.0f) * 0.25f * gs - 0.5f;
    float ly = (cy + 2.0f) * 0.25f * gs - 0.5f;
    float lz = (cz + 2.0f) * 0.25f * gs - 0.5f;

    float fx = floorf(lx), fy = floorf(ly), fz = floorf(lz);
    float wx1 = lx - fx, wy1 = ly - fy, wz1 = lz - fz;
    float wx0 = 1.0f - wx1, wy0 = 1.0f - wy1, wz0 = 1.0f - wz1;

    unsigned bx = (unsigned)(int)fx;
    unsigned by = (unsigned)(int)fy;
    unsigned bz = (unsigned)(int)fz;

    unsigned hy0 = by * PI2;
    unsigned hz0 = bz * PI3;
    unsigned dy  = hy0 ^ ((by + 1u) * PI2);
    unsigned dz  = hz0 ^ ((bz + 1u) * PI3);

    const float4* __restrict__ tab = tables + ((size_t)l << HASH_BITS);

    unsigned h000 = bx ^ hy0 ^ hz0;
    unsigned i000 = h000 & HASH_MASK;
    unsigned i001 = (h000 ^ dz) & HASH_MASK;
    unsigned i010 = (h000 ^ dy) & HASH_MASK;
    unsigned i011 = (h000 ^ dy ^ dz) & HASH_MASK;

    // weights, same association as reference: (wx*wy)*wz
    float w000 = (wx0 * wy0) * wz0;
    float w001 = (wx0 * wy0) * wz1;
    float w010 = (wx0 * wy1) * wz0;
    float w011 = (wx0 * wy1) * wz1;
    float w100 = (wx1 * wy0) * wz0;
    float w101 = (wx1 * wy0) * wz1;
    float w110 = (wx1 * wy1) * wz0;
    float w111 = (wx1 * wy1) * wz1;

    float ax, ay, az, aw;

    if ((bx & 1u) == 0u) {
        // Even bx: x0/x1 corners table-adjacent (i, i^1). 4 x 32B loads.
        float4 a0, b0, a1, b1, a2, b2, a3, b3;
        ld_pair(tab + (i000 & ~1u), a0, b0);
        ld_pair(tab + (i001 & ~1u), a1, b1);
        ld_pair(tab + (i010 & ~1u), a2, b2);
        ld_pair(tab + (i011 & ~1u), a3, b3);

        float wl0 = (i000 & 1u) ? w100 : w000, wh0 = (i000 & 1u) ? w000 : w100;
        float wl1 = (i001 & 1u) ? w101 : w001, wh1 = (i001 & 1u) ? w001 : w101;
        float wl2 = (i010 & 1u) ? w110 : w010, wh2 = (i010 & 1u) ? w010 : w110;
        float wl3 = (i011 & 1u) ? w111 : w011, wh3 = (i011 & 1u) ? w011 : w111;

        ax = a0.x * wl0; ay = a0.y * wl0; az = a0.z * wl0; aw = a0.w * wl0;
        ax = fmaf(b0.x, wh0, ax); ay = fmaf(b0.y, wh0, ay); az = fmaf(b0.z, wh0, az); aw = fmaf(b0.w, wh0, aw);
        ax = fmaf(a1.x, wl1, ax); ay = fmaf(a1.y, wl1, ay); az = fmaf(a1.z, wl1, az); aw = fmaf(a1.w, wl1, aw);
        ax = fmaf(b1.x, wh1, ax); ay = fmaf(b1.y, wh1, ay); az = fmaf(b1.z, wh1, az); aw = fmaf(b1.w, wh1, aw);
        ax = fmaf(a2.x, wl2, ax); ay = fmaf(a2.y, wl2, ay); az = fmaf(a2.z, wl2, az); aw = fmaf(a2.w, wl2, aw);
        ax = fmaf(b2.x, wh2, ax); ay = fmaf(b2.y, wh2, ay); az = fmaf(b2.z, wh2, az); aw = fmaf(b2.w, wh2, aw);
        ax = fmaf(a3.x, wl3, ax); ay = fmaf(a3.y, wl3, ay); az = fmaf(a3.z, wl3, az); aw = fmaf(a3.w, wl3, aw);
        ax = fmaf(b3.x, wh3, ax); ay = fmaf(b3.y, wh3, ay); az = fmaf(b3.z, wh3, az); aw = fmaf(b3.w, wh3, aw);
    } else {
        // Odd bx: no adjacency; 8 x 16B gathers with evict_last policy.
        unsigned h100 = h000 ^ bx ^ (bx + 1u);
        unsigned i100 = h100 & HASH_MASK;
        unsigned i101 = (h100 ^ dz) & HASH_MASK;
        unsigned i110 = (h100 ^ dy) & HASH_MASK;
        unsigned i111 = (h100 ^ dy ^ dz) & HASH_MASK;

        float4 v000 = ld_tab(tab + i000, pol);
        float4 v001 = ld_tab(tab + i001, pol);
        float4 v010 = ld_tab(tab + i010, pol);
        float4 v011 = ld_tab(tab + i011, pol);
        float4 v100 = ld_tab(tab + i100, pol);
        float4 v101 = ld_tab(tab + i101, pol);
        float4 v110 = ld_tab(tab + i110, pol);
        float4 v111 = ld_tab(tab + i111, pol);

        ax = v000.x * w000; ay = v000.y * w000; az = v000.z * w000; aw = v000.w * w000;
        ax = fmaf(v001.x, w001, ax); ay = fmaf(v001.y, w001, ay); az = fmaf(v001.z, w001, az); aw = fmaf(v001.w, w001, aw);
        ax = fmaf(v010.x, w010, ax); ay = fmaf(v010.y, w010, ay); az = fmaf(v010.z, w010, az); aw = fmaf(v010.w, w010, aw);
        ax = fmaf(v011.x, w011, ax); ay = fmaf(v011.y, w011, ay); az = fmaf(v011.z, w011, az); aw = fmaf(v011.w, w011, aw);
        ax = fmaf(v100.x, w100, ax); ay = fmaf(v100.y, w100, ay); az = fmaf(v100.z, w100, az); aw = fmaf(v100.w, w100, aw);
        ax = fmaf(v101.x, w101, ax); ay = fmaf(v101.y, w101, ay); az = fmaf(v101.z, w101, az); aw = fmaf(v101.w, w101, aw);
        ax = fmaf(v110.x, w110, ax); ay = fmaf(v110.y, w110, ay); az = fmaf(v110.z, w110, az); aw = fmaf(v110.w, w110, aw);
        ax = fmaf(v111.x, w111, ax); ay = fmaf(v111.y, w111, ay); az = fmaf(v111.z, w111, az); aw = fmaf(v111.w, w111, aw);
    }

    float4 r;
    r.x = ax * 10.0f;
    r.y = ay * 10.0f;
    r.z = az * 10.0f;
    r.w = aw * 10.0f;
    st_stream(out + (size_t)n * NUM_LEVELS + l, r);   // == out + tid, coalesced
}

extern "C" void kernel_launch(void* const* d_in, const int* in_sizes, int n_in,
                              void* d_out, int out_size)
{
    const float*  x      = (const float*)d_in[0];
    const float4* tables = (const float4*)d_in[1];
    float4*       out    = (float4*)d_out;

    int n_points = in_sizes[0] / 3;
    int total = n_points * NUM_LEVELS;
    int block = 256;
    int grid = (total + block - 1) / block;
    hashenc_kernel<<<grid, block>>>(x, tables, out, n_points);
}